// round 10
// baseline (speedup 1.0000x reference)
#include <cuda_runtime.h>
#include <float.h>

// x: [B=64, N=4096, D=1024] fp32, top-K=16 along N per (b,d), then mean -> out [B, D] fp32.
// One thread per (b,d) column. Warp lanes span consecutive d -> fully coalesced
// 128B accesses. Top-16 kept as a sorted register array; hot path is a single
// compare against the current 16th-largest value.

#define B_DIM 64
#define N_DIM 4096
#define D_DIM 1024
#define K_TOP 16
#define NCOL (B_DIM * D_DIM)   // 65536 threads total
#define TPB 256
#define UNROLL 16

__global__ __launch_bounds__(TPB, 4)
void topk_mean_kernel(const float* __restrict__ x, float* __restrict__ out) {
    const int tid = blockIdx.x * TPB + threadIdx.x;
    const int b = tid >> 10;        // tid / 1024
    const int d = tid & 1023;       // tid % 1024

    const float* __restrict__ col = x + ((size_t)b * N_DIM) * D_DIM + d;

    // Sorted descending: top[0] >= top[1] >= ... >= top[15]
    float top[K_TOP];
#pragma unroll
    for (int j = 0; j < K_TOP; ++j) top[j] = -FLT_MAX;

#pragma unroll 1
    for (int n = 0; n < N_DIM; n += UNROLL) {
        // Batch UNROLL independent loads for MLP; offsets are compile-time
        // immediates (u * 4096 B) off an advancing base pointer.
        float buf[UNROLL];
#pragma unroll
        for (int u = 0; u < UNROLL; ++u)
            buf[u] = __ldg(col + (size_t)u * D_DIM);
        col += (size_t)UNROLL * D_DIM;

#pragma unroll
        for (int u = 0; u < UNROLL; ++u) {
            float v = buf[u];
            if (v > top[K_TOP - 1]) {
                // Bubble v into place (branchless compare-swap chain,
                // all constant indices -> stays in registers).
                top[K_TOP - 1] = v;
#pragma unroll
                for (int j = K_TOP - 1; j > 0; --j) {
                    float hi = fmaxf(top[j - 1], top[j]);
                    float lo = fminf(top[j - 1], top[j]);
                    top[j - 1] = hi;
                    top[j] = lo;
                }
            }
        }
    }

    float s = 0.0f;
#pragma unroll
    for (int j = 0; j < K_TOP; ++j) s += top[j];
    out[tid] = s * (1.0f / K_TOP);
}

extern "C" void kernel_launch(void* const* d_in, const int* in_sizes, int n_in,
                              void* d_out, int out_size) {
    const float* x = (const float*)d_in[0];
    float* out = (float*)d_out;
    topk_mean_kernel<<<NCOL / TPB, TPB>>>(x, out);
}

// round 11
// speedup vs baseline: 1.0968x; 1.0968x over previous
#include <cuda_runtime.h>
#include <float.h>

// x: [B=64, N=4096, D=1024] fp32. Per (b,d): top-16 along N, then mean -> out [B, D].
// One thread per (b,d) column; warp lanes span consecutive d (coalesced 128B).
// Top-16 held sorted-descending in registers; hot path = 1 compare vs top[15].
// Double-buffered 16-load batches keep ~32 LDGs in flight per thread while the
// FMNMX insert chain runs, hiding DRAM latency.

#define B_DIM 64
#define N_DIM 4096
#define D_DIM 1024
#define K_TOP 16
#define NCOL (B_DIM * D_DIM)
#define TPB 64
#define U 16
#define NBATCH (N_DIM / U)   // 256

__device__ __forceinline__ void load_batch(float* __restrict__ buf,
                                           const float* __restrict__ p) {
#pragma unroll
    for (int u = 0; u < U; ++u)
        buf[u] = __ldcs(p + (size_t)u * D_DIM);
}

__device__ __forceinline__ void process_batch(float* __restrict__ top,
                                              const float* __restrict__ buf) {
#pragma unroll
    for (int u = 0; u < U; ++u) {
        float v = buf[u];
        if (v > top[K_TOP - 1]) {
            top[K_TOP - 1] = v;
#pragma unroll
            for (int j = K_TOP - 1; j > 0; --j) {
                float hi = fmaxf(top[j - 1], top[j]);
                float lo = fminf(top[j - 1], top[j]);
                top[j - 1] = hi;
                top[j] = lo;
            }
        }
    }
}

__global__ __launch_bounds__(TPB, 8)
void topk_mean_kernel(const float* __restrict__ x, float* __restrict__ out) {
    const int tid = blockIdx.x * TPB + threadIdx.x;
    const int b = tid >> 10;
    const int d = tid & 1023;

    const float* __restrict__ p = x + ((size_t)b * N_DIM) * D_DIM + d;

    float top[K_TOP];
#pragma unroll
    for (int j = 0; j < K_TOP; ++j) top[j] = -FLT_MAX;

    float bufA[U], bufB[U];

    // Preload batch 0.
    load_batch(bufA, p);
    p += (size_t)U * D_DIM;

    // Pairs: load next batch before processing current one (ping-pong).
#pragma unroll 1
    for (int pair = 0; pair < NBATCH / 2 - 1; ++pair) {
        load_batch(bufB, p);            // batch 2*pair+1
        p += (size_t)U * D_DIM;
        process_batch(top, bufA);
        load_batch(bufA, p);            // batch 2*pair+2
        p += (size_t)U * D_DIM;
        process_batch(top, bufB);
    }
    // Epilogue: last pair (batches 254, 255).
    load_batch(bufB, p);
    process_batch(top, bufA);
    process_batch(top, bufB);

    float s = 0.0f;
#pragma unroll
    for (int j = 0; j < K_TOP; ++j) s += top[j];
    out[tid] = s * (1.0f / K_TOP);
}

extern "C" void kernel_launch(void* const* d_in, const int* in_sizes, int n_in,
                              void* d_out, int out_size) {
    const float* x = (const float*)d_in[0];
    float* out = (float*)d_out;
    topk_mean_kernel<<<NCOL / TPB, TPB>>>(x, out);
}